// round 1
// baseline (speedup 1.0000x reference)
#include <cuda_runtime.h>

// Shapes fixed by the problem: [B=4, C=32, H=1024, W=1024] fp32 -> [B,H,W] fp32
#define CCH 32
#define HH  1024
#define WW  1024
#define RAD 25   // kernel_radius = W // 40 = 25 (window = 51)

// 16 MB scratch for channel-summed + box-w'd intermediate
__device__ float g_scratch[4 * HH * WW];

// ---------------------------------------------------------------------------
// Kernel A: per (b,h) row — gradient magnitude, channel sum, box filter along w
// block = 256 threads, each handles 4 consecutive w (float4)
// ---------------------------------------------------------------------------
__global__ __launch_bounds__(256) void grad_boxw_kernel(const float* __restrict__ x) {
    const int bh   = blockIdx.x;
    const int b    = bh >> 10;          // / HH
    const int h    = bh & (HH - 1);
    const int tid  = threadIdx.x;
    const int lane = tid & 31;
    const int wid  = tid >> 5;
    const int w0   = tid << 2;

    const float* xb = x + (size_t)b * CCH * HH * WW;

    float a0 = 0.f, a1 = 0.f, a2 = 0.f, a3 = 0.f;

    #pragma unroll 4
    for (int c = 0; c < CCH; ++c) {
        const float* row = xb + ((size_t)c * HH + h) * WW;
        float4 cur = *reinterpret_cast<const float4*>(row + w0);
        float4 top;
        if (h > 0) top = *reinterpret_cast<const float4*>(row - WW + w0);
        else       top = make_float4(0.f, 0.f, 0.f, 0.f);

        // left neighbor of element 0: lane-1's cur.w, or scalar load at warp edge
        float left = __shfl_up_sync(0xffffffffu, cur.w, 1);
        if (lane == 0) left = (w0 > 0) ? row[w0 - 1] : 0.f;

        float dx0 = left  - cur.x;
        float dx1 = cur.x - cur.y;
        float dx2 = cur.y - cur.z;
        float dx3 = cur.z - cur.w;
        float dy0 = top.x - cur.x;
        float dy1 = top.y - cur.y;
        float dy2 = top.z - cur.z;
        float dy3 = top.w - cur.w;

        float s0 = dx0 * dx0 + dy0 * dy0;
        float s1 = dx1 * dx1 + dy1 * dy1;
        float s2 = dx2 * dx2 + dy2 * dy2;
        float s3 = dx3 * dx3 + dy3 * dy3;

        a0 += (s0 > 0.f) ? s0 * rsqrtf(s0) : 0.f;
        a1 += (s1 > 0.f) ? s1 * rsqrtf(s1) : 0.f;
        a2 += (s2 > 0.f) ? s2 * rsqrtf(s2) : 0.f;
        a3 += (s3 > 0.f) ? s3 * rsqrtf(s3) : 0.f;
    }

    // ---- block-wide inclusive prefix sum over the 1024 row values ----
    __shared__ float S[WW + 1];   // S[0] = 0, S[w+1] = inclusive prefix at w
    __shared__ float wsum[8];

    float p0 = a0;
    float p1 = p0 + a1;
    float p2 = p1 + a2;
    float p3 = p2 + a3;
    float t  = p3;                 // this thread's local sum

    // inclusive warp scan of t
    float sc = t;
    #pragma unroll
    for (int o = 1; o < 32; o <<= 1) {
        float v = __shfl_up_sync(0xffffffffu, sc, o);
        if (lane >= o) sc += v;
    }
    if (lane == 31) wsum[wid] = sc;
    __syncthreads();
    if (wid == 0) {
        float wv = (lane < 8) ? wsum[lane] : 0.f;
        float ws = wv;
        #pragma unroll
        for (int o = 1; o < 8; o <<= 1) {
            float v = __shfl_up_sync(0xffffffffu, ws, o);
            if (lane >= o) ws += v;
        }
        if (lane < 8) wsum[lane] = ws - wv;  // exclusive warp offsets
    }
    __syncthreads();

    float base = wsum[wid] + (sc - t);  // exclusive offset for this thread
    if (tid == 0) S[0] = 0.f;
    S[w0 + 1] = base + p0;
    S[w0 + 2] = base + p1;
    S[w0 + 3] = base + p2;
    S[w0 + 4] = base + p3;
    __syncthreads();

    // box sum along w: out[w] = sum g[w-RAD .. w+RAD] clipped = S[hi+1] - S[lo]
    float* grow = g_scratch + ((size_t)b * HH + h) * WW;
    #pragma unroll
    for (int i = 0; i < 4; ++i) {
        int w  = w0 + i;
        int lo = max(0, w - RAD);
        int hi = min(WW - 1, w + RAD);
        grow[w] = S[hi + 1] - S[lo];
    }
}

// ---------------------------------------------------------------------------
// Kernel B: box filter along h (sliding window per column, coalesced)
// grid = (WW/256, HH/HT, B), block = 256 threads (one column each)
// ---------------------------------------------------------------------------
#define HT 32
__global__ __launch_bounds__(256) void boxh_kernel(float* __restrict__ out) {
    const int w  = blockIdx.x * 256 + threadIdx.x;
    const int h0 = blockIdx.y * HT;
    const int b  = blockIdx.z;

    const float* gp = g_scratch + (size_t)b * HH * WW + w;
    float*       op = out       + (size_t)b * HH * WW + w;

    float s = 0.f;
    const int jlo = max(0, h0 - RAD);
    const int jhi = min(HH - 1, h0 + RAD);
    for (int j = jlo; j <= jhi; ++j) s += gp[(size_t)j * WW];

    #pragma unroll
    for (int i = 0; i < HT; ++i) {
        const int h = h0 + i;
        op[(size_t)h * WW] = s;
        const int add = h + RAD + 1;
        const int sub = h - RAD;
        if (add < HH) s += gp[(size_t)add * WW];
        if (sub >= 0) s -= gp[(size_t)sub * WW];
    }
}

// ---------------------------------------------------------------------------

extern "C" void kernel_launch(void* const* d_in, const int* in_sizes, int n_in,
                              void* d_out, int out_size) {
    const float* x = (const float*)d_in[0];
    float* out = (float*)d_out;

    const int n = in_sizes[0];
    const int B = n / (CCH * HH * WW);   // 4

    grad_boxw_kernel<<<B * HH, 256>>>(x);

    dim3 gridB(WW / 256, HH / HT, B);
    boxh_kernel<<<gridB, 256>>>(out);
}